// round 11
// baseline (speedup 1.0000x reference)
#include <cuda_runtime.h>
#include <cuda_fp16.h>
#include <cstdint>

// Problem constants
#define Bq 8
#define Dd 256
#define Tt 2048
#define Kk 8192
#define NQ (Bq * Tt)          // 16384 queries
#define NEL (Bq * Dd * Tt)    // 4194304 z elements
#define NGRP (Kk / 8)         // 1024 groups of 8 codes

#define EPS 0.010f
#define CAND_CAP (2 * 1024 * 1024)

// int8 quantization scales
#define SZ 22.0f              // z_q = round(22*z), |z|<5.6 -> fits int8
#define SC 32512.0f           // c_q = round(127*256*c), |c|<=1/256 -> +/-127
#define DSCALE (2.0f / (SZ * SC))   // d = cc - DSCALE*acc

// Phase-1 tiling (int8: 1 B/elem)
#define PM 128
#define PN 128
#define PK 64                 // gemm-K chunk = 64 int8 = 64 B/row
#define NCHUNK (Dd / PK)      // 4
#define ROWB8 80              // smem row stride bytes (64 data + 16 pad)
#define STAGE_BYTES ((PM + PN) * ROWB8)       // 20480
#define SMEM_DYN (2 * STAGE_BYTES)            // 40960

// Device scratch (static; runtime allocation is forbidden)
__device__ __align__(128) float   g_zt[NQ * Dd];    // z transposed [q][d] fp32
__device__ __align__(128) int8_t  g_z8[NQ * Dd];    // int8 z (x22)
__device__ __align__(128) int8_t  g_cb8[Kk * Dd];   // int8 codebook (x32512)
__device__ __align__(128) float   g_gmin[(size_t)NGRP * NQ];
__device__ __align__(128) unsigned g_m1[NQ];        // per-query encoded min
__device__ __align__(128) float   g_zz[NQ];
__device__ __align__(128) float   g_cc[Kk];
__device__ __align__(128) unsigned long long g_key[NQ];
__device__ __align__(128) unsigned int g_cand[CAND_CAP];
__device__ int    g_ncand;
__device__ double g_loss_sum;

// ---------------------------------------------------------------------------
__device__ __forceinline__ uint32_t smem_u32(const void* p) {
    uint32_t a;
    asm("{ .reg .u64 t; cvta.to.shared.u64 t, %1; cvt.u32.u64 %0, t; }" : "=r"(a) : "l"(p));
    return a;
}
__device__ __forceinline__ unsigned fenc(float f) {
    int b = __float_as_int(f);
    return b >= 0 ? ((unsigned)b | 0x80000000u) : ~(unsigned)b;
}
__device__ __forceinline__ float fdec(unsigned k) {
    return (k & 0x80000000u) ? __int_as_float((int)(k & 0x7fffffffu))
                             : __int_as_float((int)~k);
}
#define CP16(dst, src) \
    asm volatile("cp.async.cg.shared.global [%0], [%1], 16;" :: "r"(dst), "l"(src) : "memory")
#define LDM4(r0, r1, r2, r3, a) \
    asm volatile("ldmatrix.sync.aligned.m8n8.x4.shared.b16 {%0,%1,%2,%3}, [%4];" \
        : "=r"(r0), "=r"(r1), "=r"(r2), "=r"(r3) : "r"(a))
// s8 IMMA, k32: fragment byte layout identical to f16 k16 (4 s8 = 2 b16)
#define MMA16832S8(c0, c1, c2, c3, a0, a1, a2, a3, b0, b1) \
    asm volatile("mma.sync.aligned.m16n8k32.row.col.s32.s8.s8.s32 " \
        "{%0,%1,%2,%3}, {%4,%5,%6,%7}, {%8,%9}, {%0,%1,%2,%3};" \
        : "+r"(c0), "+r"(c1), "+r"(c2), "+r"(c3) \
        : "r"(a0), "r"(a1), "r"(a2), "r"(a3), "r"(b0), "r"(b1))

// ---------------------------------------------------------------------------
// Exact sequential fp32 sums of squares (rounding order validated in R1)
__global__ void zz_kernel(const float* __restrict__ z) {
    int i = blockIdx.x * blockDim.x + threadIdx.x;
    if (i >= NQ) return;
    int b = i / Tt, t = i % Tt;
    const float* p = z + (size_t)b * Dd * Tt + t;
    float acc = 0.0f;
    for (int d = 0; d < Dd; d++) {
        float v = p[(size_t)d * Tt];
        acc = __fadd_rn(acc, __fmul_rn(v, v));
    }
    g_zz[i] = acc;
}

// cc (exact sequential) + global init fused
__global__ void cc_init_kernel(const float* __restrict__ cb) {
    int i = blockIdx.x * blockDim.x + threadIdx.x;
    if (i < Kk) {
        const float* p = cb + (size_t)i * Dd;
        float acc = 0.0f;
        for (int d = 0; d < Dd; d++) {
            float v = p[d];
            acc = __fadd_rn(acc, __fmul_rn(v, v));
        }
        g_cc[i] = acc;
    }
    if (i < NQ) { g_key[i] = ~0ull; g_m1[i] = 0xFFFFFFFFu; }
    if (i == 0) { g_loss_sum = 0.0; g_ncand = 0; }
}

// codebook -> int8 (x32512, clamp)
__global__ void prep_cb_kernel(const float* __restrict__ cb) {
    int i = blockIdx.x * blockDim.x + threadIdx.x;
    if (i < Kk * Dd) {
        int v = __float2int_rn(cb[i] * SC);
        v = v > 127 ? 127 : (v < -127 ? -127 : v);
        g_cb8[i] = (int8_t)v;
    }
}

// Transpose z (B,D,T) -> [q][d]; write fp32 + int8 copies.
__global__ void prep_z_kernel(const float* __restrict__ z) {
    __shared__ float tile[32][33];
    int b = blockIdx.z, t0 = blockIdx.x * 32, d0 = blockIdx.y * 32;
    int tx = threadIdx.x, ty = threadIdx.y;   // 32 x 8
    #pragma unroll
    for (int r = 0; r < 4; r++) {
        int d = d0 + ty + r * 8;
        tile[ty + r * 8][tx] = z[(size_t)b * Dd * Tt + (size_t)d * Tt + t0 + tx];
    }
    __syncthreads();
    #pragma unroll
    for (int r = 0; r < 4; r++) {
        int tt = t0 + ty + r * 8;
        float v = tile[tx][ty + r * 8];
        size_t o = (size_t)(b * Tt + tt) * Dd + d0 + tx;
        g_zt[o] = v;
        int q8 = __float2int_rn(v * SZ);
        q8 = q8 > 127 ? 127 : (q8 < -127 ? -127 : q8);
        g_z8[o] = (int8_t)q8;
    }
}

// ---------------------------------------------------------------------------
// Phase 1: int8 mma.sync m16n8k32 GEMM (2x MAC/instr vs f16 k16; byte-wise
// identical fragment mapping, validated structure carried from R5-R10).
// acc_int = sum z_q*c_q ~ 715264 * dot. Epilogue v = cc - DSCALE*acc.
__global__ void __launch_bounds__(256, 2) phase1_kernel() {
    extern __shared__ char sm8[];
    __shared__ unsigned srowmin[PM];

    int tid = threadIdx.x, wid = tid >> 5, l = tid & 31;
    int wm = wid & 3, wn = wid >> 2;
    int q0 = blockIdx.y * PM, k0 = blockIdx.x * PN;

    if (tid < PM) srowmin[tid] = 0xFFFFFFFFu;

    int acc[2][8][4];
    #pragma unroll
    for (int mi = 0; mi < 2; mi++)
        #pragma unroll
        for (int ni = 0; ni < 8; ni++)
            #pragma unroll
            for (int j = 0; j < 4; j++) acc[mi][ni][j] = 0;

    uint32_t s0 = smem_u32(&sm8[0]);
    const uint32_t bOffB = (uint32_t)PM * ROWB8;

    int rA = wm * 32 + (l & 15), hA = (l >> 4) & 1;
    int rB = wn * 64 + (l & 15), hB = (l >> 4) & 1;
    uint32_t aoff = (uint32_t)(rA * ROWB8 + hA * 16);
    uint32_t boff = (uint32_t)(rB * ROWB8 + hB * 16);
    int rot = wid & 1;                       // stagger over the 2 k32 steps

    auto issue = [&](int c) {
        uint32_t st = s0 + (uint32_t)(c & 1) * STAGE_BYTES;
        int d0 = c * PK;
        #pragma unroll
        for (int i = 0; i < 4; i++) {
            int idx = tid + i * 256;          // 0..1023
            int row = idx >> 2, sec = idx & 3;
            const int8_t* src = (row < PM)
                ? g_z8 + (size_t)(q0 + row) * Dd + d0 + sec * 16
                : g_cb8 + (size_t)(k0 + row - PM) * Dd + d0 + sec * 16;
            uint32_t dst = st + ((row < PM)
                ? (uint32_t)(row * ROWB8 + sec * 16)
                : (bOffB + (uint32_t)((row - PM) * ROWB8 + sec * 16)));
            CP16(dst, src);
        }
        asm volatile("cp.async.commit_group;" ::: "memory");
    };

    issue(0);
    for (int c = 0; c < NCHUNK; c++) {
        if (c + 1 < NCHUNK) {
            issue(c + 1);
            asm volatile("cp.async.wait_group 1;" ::: "memory");
        } else {
            asm volatile("cp.async.wait_group 0;" ::: "memory");
        }
        __syncthreads();
        uint32_t st = s0 + (uint32_t)(c & 1) * STAGE_BYTES;
        uint32_t bA = st, bB = st + bOffB;
        #pragma unroll
        for (int ks = 0; ks < 2; ks++) {           // 2 x k32 within 64B chunk
            int kk = (ks + rot) & 1;
            uint32_t kb = (uint32_t)(kk * 32);     // 32 B per k32 step
            uint32_t af[2][4], bf[4][4];
            #pragma unroll
            for (int mi = 0; mi < 2; mi++)
                LDM4(af[mi][0], af[mi][1], af[mi][2], af[mi][3],
                     bA + aoff + (uint32_t)(mi * 16 * ROWB8) + kb);
            #pragma unroll
            for (int p = 0; p < 4; p++)
                LDM4(bf[p][0], bf[p][1], bf[p][2], bf[p][3],
                     bB + boff + (uint32_t)(p * 16 * ROWB8) + kb);
            #pragma unroll
            for (int mi = 0; mi < 2; mi++)
                #pragma unroll
                for (int p = 0; p < 4; p++) {
                    MMA16832S8(acc[mi][2*p][0], acc[mi][2*p][1], acc[mi][2*p][2], acc[mi][2*p][3],
                               af[mi][0], af[mi][1], af[mi][2], af[mi][3],
                               bf[p][0], bf[p][2]);
                    MMA16832S8(acc[mi][2*p+1][0], acc[mi][2*p+1][1], acc[mi][2*p+1][2], acc[mi][2*p+1][3],
                               af[mi][0], af[mi][1], af[mi][2], af[mi][3],
                               bf[p][1], bf[p][3]);
                }
        }
        __syncthreads();
    }

    // Epilogue: v = cc - DSCALE*acc  (same positions as f32 fragment layout)
    int gq = l >> 2;
    #pragma unroll
    for (int mi = 0; mi < 2; mi++) {
        int rl0 = wm * 32 + mi * 16 + gq;
        float rmin0 = 3.4e38f, rmin8 = 3.4e38f;
        #pragma unroll
        for (int ni = 0; ni < 8; ni++) {
            int col = k0 + wn * 64 + ni * 8 + (l & 3) * 2;
            float cc0 = g_cc[col], cc1 = g_cc[col + 1];
            float m0 = fminf(fmaf(__int2float_rn(acc[mi][ni][0]), -DSCALE, cc0),
                             fmaf(__int2float_rn(acc[mi][ni][1]), -DSCALE, cc1));
            float m8 = fminf(fmaf(__int2float_rn(acc[mi][ni][2]), -DSCALE, cc0),
                             fmaf(__int2float_rn(acc[mi][ni][3]), -DSCALE, cc1));
            m0 = fminf(m0, __shfl_xor_sync(~0u, m0, 1));
            m0 = fminf(m0, __shfl_xor_sync(~0u, m0, 2));
            m8 = fminf(m8, __shfl_xor_sync(~0u, m8, 1));
            m8 = fminf(m8, __shfl_xor_sync(~0u, m8, 2));
            if ((l & 3) == 0) {
                size_t g = (size_t)((k0 + wn * 64 + ni * 8) >> 3);
                g_gmin[g * NQ + q0 + rl0] = m0;
                g_gmin[g * NQ + q0 + rl0 + 8] = m8;
                rmin0 = fminf(rmin0, m0);
                rmin8 = fminf(rmin8, m8);
            }
        }
        if ((l & 3) == 0) {
            atomicMin(&srowmin[rl0], fenc(rmin0));
            atomicMin(&srowmin[rl0 + 8], fenc(rmin8));
        }
    }
    __syncthreads();
    if (tid < PM) atomicMin(&g_m1[q0 + tid], srowmin[tid]);
}

// ---------------------------------------------------------------------------
// Phase 2a: flag groups with v <= m1 + EPS (single pass; m1 from phase1).
__global__ void __launch_bounds__(256) cand_kernel() {
    int q0 = blockIdx.x * 32;
    int wid = threadIdx.x >> 5, l = threadIdx.x & 31;
    int q = q0 + l;
    float thr = fdec(g_m1[q]) + EPS;
    for (int g = wid; g < NGRP; g += 8) {
        if (g_gmin[(size_t)g * NQ + q] <= thr) {
            int pos = atomicAdd(&g_ncand, 1);
            if (pos < CAND_CAP) g_cand[pos] = ((unsigned)q << 10) | (unsigned)g;
        }
    }
}

// Phase 2b: exact fp32 rescore of flagged groups; packed atomicMin => argmin
// with first-index tie-break (reference rounding formula, R1-validated).
__global__ void __launch_bounds__(256) rescore_kernel(const float* __restrict__ cb) {
    int gw = (blockIdx.x * blockDim.x + threadIdx.x) >> 5;
    int l = threadIdx.x & 31;
    int nwarps = (gridDim.x * blockDim.x) >> 5;
    int n = g_ncand; if (n > CAND_CAP) n = CAND_CAP;
    for (int c = gw; c < n; c += nwarps) {
        unsigned e = g_cand[c];
        int q = e >> 10, g = e & 1023;
        const float* zr = g_zt + (size_t)q * Dd;
        float zzv = g_zz[q];
        unsigned long long best = ~0ull;
        #pragma unroll 1
        for (int kk = 0; kk < 8; kk++) {
            int k = g * 8 + kk;
            const float* cr = cb + (size_t)k * Dd;
            float p = 0.0f;
            #pragma unroll
            for (int j = 0; j < 8; j++) {
                int d = l * 8 + j;
                p = __fadd_rn(p, __fmul_rn(zr[d], cr[d]));
            }
            #pragma unroll
            for (int o = 16; o > 0; o >>= 1)
                p = __fadd_rn(p, __shfl_xor_sync(~0u, p, o));
            float dd = __fadd_rn(__fadd_rn(zzv, __fmul_rn(-2.0f, p)), g_cc[k]);
            unsigned long long key =
                ((unsigned long long)__float_as_uint(dd) << 32) | (unsigned)k;
            if (key < best) best = key;
        }
        if (l == 0) atomicMin(&g_key[q], best);
    }
}

// ---------------------------------------------------------------------------
// Gather: coalesced via smem transpose of the gathered codebook rows.
__global__ void gather_kernel(const float* __restrict__ z,
                              const float* __restrict__ cb,
                              float* __restrict__ out, long long out_size) {
    __shared__ float tile[32][33];
    __shared__ double ssum[256];
    int b = blockIdx.z, d0 = blockIdx.y * 32, t0 = blockIdx.x * 32;
    int tx = threadIdx.x, ty = threadIdx.y;
    #pragma unroll
    for (int r = 0; r < 4; r++) {
        int t = ty + r * 8;
        int q = b * Tt + t0 + t;
        int idx = (int)(unsigned)(g_key[q] & 0xffffffffu);
        tile[t][tx] = cb[(size_t)idx * Dd + d0 + tx];     // lane spans d: coalesced
    }
    __syncthreads();
    double local = 0.0;
    #pragma unroll
    for (int r = 0; r < 4; r++) {
        int d = d0 + ty + r * 8;
        long long o = ((long long)b * Dd + d) * Tt + t0 + tx;
        float zv = z[o];
        float zq = tile[tx][ty + r * 8];
        float diff = __fadd_rn(zq, -zv);
        if (o < out_size) out[o] = __fadd_rn(zv, diff);   // lane spans t: coalesced
        local += (double)__fmul_rn(diff, diff);
    }
    int tid = ty * 32 + tx;
    ssum[tid] = local;
    __syncthreads();
    for (int s = 128; s > 0; s >>= 1) {
        if (tid < s) ssum[tid] += ssum[tid + s];
        __syncthreads();
    }
    if (tid == 0) atomicAdd(&g_loss_sum, ssum[0]);
}

__global__ void finalize_kernel(float* __restrict__ out, long long out_size) {
    int i = blockIdx.x * blockDim.x + threadIdx.x;
    if (out_size >= NEL + NQ && i < NQ)
        out[NEL + i] = (float)(unsigned)(g_key[i] & 0xffffffffu);
    if (i == 0 && out_size >= NEL + NQ + 1) {
        float m = (float)(g_loss_sum / (double)NEL);
        out[NEL + NQ] = __fadd_rn(m, __fmul_rn(0.1f, m));
    }
}

// ---------------------------------------------------------------------------
extern "C" void kernel_launch(void* const* d_in, const int* in_sizes, int n_in,
                              void* d_out, int out_size) {
    const float* z  = (const float*)d_in[0];
    const float* cb = (const float*)d_in[1];
    if (n_in >= 2 && in_sizes[0] == Kk * Dd && in_sizes[1] == NEL) {
        const float* tmp = z; z = cb; cb = tmp;
    }
    float* out = (float*)d_out;
    long long osz = out_size;

    cudaFuncSetAttribute(phase1_kernel,
                         cudaFuncAttributeMaxDynamicSharedMemorySize, SMEM_DYN);

    // phase1 kept at launch index 3 (the launch ncu captures)
    prep_cb_kernel<<<(Kk * Dd + 255) / 256, 256>>>(cb);                 // 0
    dim3 tb(32, 8), tg(Tt / 32, Dd / 32, Bq);
    prep_z_kernel<<<tg, tb>>>(z);                                       // 1
    cc_init_kernel<<<(NQ + 255) / 256, 256>>>(cb);                      // 2
    dim3 g1(Kk / PN, NQ / PM);
    phase1_kernel<<<g1, 256, SMEM_DYN>>>();                             // 3
    zz_kernel<<<(NQ + 255) / 256, 256>>>(z);                            // 4
    cand_kernel<<<NQ / 32, 256>>>();                                    // 5
    rescore_kernel<<<512, 256>>>(cb);                                   // 6
    dim3 gg(Tt / 32, Dd / 32, Bq);
    gather_kernel<<<gg, tb>>>(z, cb, out, osz);                         // 7
    finalize_kernel<<<(NQ + 255) / 256, 256>>>(out, osz);               // 8
}

// round 12
// speedup vs baseline: 1.5662x; 1.5662x over previous
#include <cuda_runtime.h>
#include <cuda_fp16.h>
#include <cstdint>

// Problem constants
#define Bq 8
#define Dd 256
#define Tt 2048
#define Kk 8192
#define NQ (Bq * Tt)          // 16384 queries
#define NEL (Bq * Dd * Tt)    // 4194304 z elements
#define NGRP (Kk / 8)         // 1024 groups of 8 codes

#define EPS 0.006f
#define CAND_CAP (2 * 1024 * 1024)

// Phase-1 tiling (R8 config: f16 inputs, f32 acc, PK=64, stagger)
#define PM 128
#define PN 128
#define PK 64
#define NCHUNK (Dd / PK)      // 4
#define ROWB 72               // smem row stride = 72 halves (64 data + 8 pad)
#define STAGE_BYTES ((PM + PN) * ROWB * 2)    // 36864
#define SMEM_DYN (2 * STAGE_BYTES)            // 73728

// prep_all block ranges
#define ZT_BLKS 4096          // z transpose tiles (64 x 8 x 8)
#define CB_BLKS 2048          // codebook fp16 convert
#define CC_BLKS 32            // cc rows
#define IN_BLKS 64            // key/m1 init
#define ZZ_BLKS 64            // zz rows
#define PREP_BLKS (ZT_BLKS + CB_BLKS + CC_BLKS + IN_BLKS + ZZ_BLKS)  // 6304

// Device scratch (static; runtime allocation is forbidden)
__device__ __align__(128) float  g_zt[NQ * Dd];     // z transposed [q][d] fp32
__device__ __align__(128) __half g_zhf[NQ * Dd];    // fp16 copy
__device__ __align__(128) __half g_cbhf[Kk * Dd];   // codebook * 256, fp16
__device__ __align__(128) __half g_gmin[(size_t)NGRP * NQ]; // fp16 approx (cc-2dot)
__device__ __align__(128) unsigned g_m1[NQ];        // per-query encoded fp32 min
__device__ __align__(128) float  g_zz[NQ];
__device__ __align__(128) float  g_cc[Kk];
__device__ __align__(128) unsigned long long g_key[NQ];
__device__ __align__(128) unsigned int g_cand[CAND_CAP];
__device__ int    g_ncand;
__device__ double g_loss_sum;

// ---------------------------------------------------------------------------
__device__ __forceinline__ uint32_t smem_u32(const void* p) {
    uint32_t a;
    asm("{ .reg .u64 t; cvta.to.shared.u64 t, %1; cvt.u32.u64 %0, t; }" : "=r"(a) : "l"(p));
    return a;
}
__device__ __forceinline__ unsigned fenc(float f) {
    int b = __float_as_int(f);
    return b >= 0 ? ((unsigned)b | 0x80000000u) : ~(unsigned)b;
}
__device__ __forceinline__ float fdec(unsigned k) {
    return (k & 0x80000000u) ? __int_as_float((int)(k & 0x7fffffffu))
                             : __int_as_float((int)~k);
}
#define CP16(dst, src) \
    asm volatile("cp.async.cg.shared.global [%0], [%1], 16;" :: "r"(dst), "l"(src) : "memory")
#define LDM4(r0, r1, r2, r3, a) \
    asm volatile("ldmatrix.sync.aligned.m8n8.x4.shared.b16 {%0,%1,%2,%3}, [%4];" \
        : "=r"(r0), "=r"(r1), "=r"(r2), "=r"(r3) : "r"(a))
#define MMA16816(c0, c1, c2, c3, a0, a1, a2, a3, b0, b1) \
    asm volatile("mma.sync.aligned.m16n8k16.row.col.f32.f16.f16.f32 " \
        "{%0,%1,%2,%3}, {%4,%5,%6,%7}, {%8,%9}, {%0,%1,%2,%3};" \
        : "+f"(c0), "+f"(c1), "+f"(c2), "+f"(c3) \
        : "r"(a0), "r"(a1), "r"(a2), "r"(a3), "r"(b0), "r"(b1))

// ---------------------------------------------------------------------------
// Mega-fused prep: z transpose + fp16 copies, cb fp16 convert, cc, zz, init.
// Disjoint blockIdx ranges; all parts independent.
__global__ void __launch_bounds__(256) prep_all_kernel(
    const float* __restrict__ z, const float* __restrict__ cb) {
    int blk = blockIdx.x, tid = threadIdx.x;

    if (blk < ZT_BLKS) {
        // z transpose (B,D,T) -> [q][d], fp32 + fp16 (validated R5 layout)
        __shared__ float tile[32][33];
        int b = blk >> 9, rem = blk & 511;
        int t0 = (rem & 63) * 32, d0 = (rem >> 6) * 32;
        int tx = tid & 31, ty = tid >> 5;          // 32 x 8
        #pragma unroll
        for (int r = 0; r < 4; r++) {
            int d = d0 + ty + r * 8;
            tile[ty + r * 8][tx] = z[(size_t)b * Dd * Tt + (size_t)d * Tt + t0 + tx];
        }
        __syncthreads();
        #pragma unroll
        for (int r = 0; r < 4; r++) {
            int tt = t0 + ty + r * 8;
            float v = tile[tx][ty + r * 8];
            size_t o = (size_t)(b * Tt + tt) * Dd + d0 + tx;
            g_zt[o] = v;
            g_zhf[o] = __float2half(v);
        }
        return;
    }
    blk -= ZT_BLKS;
    if (blk < CB_BLKS) {
        // codebook * 256 -> fp16 (exact pow2 rescale)
        #pragma unroll
        for (int k = 0; k < 4; k++) {
            int i = blk * 1024 + k * 256 + tid;
            g_cbhf[i] = __float2half(cb[i] * 256.0f);
        }
        return;
    }
    blk -= CB_BLKS;
    if (blk < CC_BLKS) {
        // cc: exact sequential fp32 sum of squares per codebook row
        int k = blk * 256 + tid;
        const float* p = cb + (size_t)k * Dd;
        float acc = 0.0f;
        for (int d = 0; d < Dd; d++) {
            float v = p[d];
            acc = __fadd_rn(acc, __fmul_rn(v, v));
        }
        g_cc[k] = acc;
        return;
    }
    blk -= CC_BLKS;
    if (blk < IN_BLKS) {
        int i = blk * 256 + tid;
        g_key[i] = ~0ull;
        g_m1[i] = 0xFFFFFFFFu;
        if (blk == 0 && tid == 0) { g_loss_sum = 0.0; g_ncand = 0; }
        return;
    }
    blk -= IN_BLKS;
    {
        // zz: exact sequential fp32 sum of squares per query (column of z)
        int i = blk * 256 + tid;
        int b = i / Tt, t = i % Tt;
        const float* p = z + (size_t)b * Dd * Tt + t;
        float acc = 0.0f;
        for (int d = 0; d < Dd; d++) {
            float v = p[(size_t)d * Tt];
            acc = __fadd_rn(acc, __fmul_rn(v, v));
        }
        g_zz[i] = acc;
    }
}

// ---------------------------------------------------------------------------
// Phase 1: fp16 mma.sync GEMM, f32 acc (R8 config, at the 512 MAC/cyc/SM
// legacy-HMMA instruction-rate wall). Epilogue: fp16 g_gmin + fp32 g_m1.
__global__ void __launch_bounds__(256, 2) phase1_kernel() {
    extern __shared__ __half smh[];
    __shared__ unsigned srowmin[PM];

    int tid = threadIdx.x, wid = tid >> 5, l = tid & 31;
    int wm = wid & 3, wn = wid >> 2;
    int q0 = blockIdx.y * PM, k0 = blockIdx.x * PN;

    if (tid < PM) srowmin[tid] = 0xFFFFFFFFu;

    float acc[2][8][4];
    #pragma unroll
    for (int mi = 0; mi < 2; mi++)
        #pragma unroll
        for (int ni = 0; ni < 8; ni++)
            #pragma unroll
            for (int j = 0; j < 4; j++) acc[mi][ni][j] = 0.0f;

    uint32_t s0 = smem_u32(&smh[0]);
    const uint32_t bOffB = (uint32_t)PM * ROWB * 2;

    int rA = wm * 32 + (l & 15), hA = (l >> 4) & 1;
    int rB = wn * 64 + (l & 15), hB = (l >> 4) & 1;
    uint32_t aoff = (uint32_t)(rA * ROWB + hA * 8) * 2;
    uint32_t boff = (uint32_t)(rB * ROWB + hB * 8) * 2;
    int rot = wid & 3;                       // per-warp k16-phase rotation

    auto issue = [&](int c) {
        uint32_t st = s0 + (uint32_t)(c & 1) * STAGE_BYTES;
        int d0 = c * PK;
        #pragma unroll
        for (int i = 0; i < 8; i++) {
            int idx = tid + i * 256;          // 0..2047
            int row = idx >> 3, sec = idx & 7;
            const __half* src = (row < PM)
                ? g_zhf + (size_t)(q0 + row) * Dd + d0 + sec * 8
                : g_cbhf + (size_t)(k0 + row - PM) * Dd + d0 + sec * 8;
            uint32_t dst = st + ((row < PM)
                ? (uint32_t)(row * ROWB + sec * 8) * 2
                : (bOffB + (uint32_t)((row - PM) * ROWB + sec * 8) * 2));
            CP16(dst, src);
        }
        asm volatile("cp.async.commit_group;" ::: "memory");
    };

    issue(0);
    for (int c = 0; c < NCHUNK; c++) {
        if (c + 1 < NCHUNK) {
            issue(c + 1);
            asm volatile("cp.async.wait_group 1;" ::: "memory");
        } else {
            asm volatile("cp.async.wait_group 0;" ::: "memory");
        }
        __syncthreads();
        uint32_t st = s0 + (uint32_t)(c & 1) * STAGE_BYTES;
        uint32_t bA = st, bB = st + bOffB;
        #pragma unroll
        for (int ks = 0; ks < 4; ks++) {
            int kk = (ks + rot) & 3;
            uint32_t kb = (uint32_t)(kk * 16) * 2;
            uint32_t af[2][4], bf[4][4];
            #pragma unroll
            for (int mi = 0; mi < 2; mi++)
                LDM4(af[mi][0], af[mi][1], af[mi][2], af[mi][3],
                     bA + aoff + (uint32_t)(mi * 16 * ROWB) * 2 + kb);
            #pragma unroll
            for (int p = 0; p < 4; p++)
                LDM4(bf[p][0], bf[p][1], bf[p][2], bf[p][3],
                     bB + boff + (uint32_t)(p * 16 * ROWB) * 2 + kb);
            #pragma unroll
            for (int mi = 0; mi < 2; mi++)
                #pragma unroll
                for (int p = 0; p < 4; p++) {
                    MMA16816(acc[mi][2*p][0], acc[mi][2*p][1], acc[mi][2*p][2], acc[mi][2*p][3],
                             af[mi][0], af[mi][1], af[mi][2], af[mi][3],
                             bf[p][0], bf[p][2]);
                    MMA16816(acc[mi][2*p+1][0], acc[mi][2*p+1][1], acc[mi][2*p+1][2], acc[mi][2*p+1][3],
                             af[mi][0], af[mi][1], af[mi][2], af[mi][3],
                             bf[p][1], bf[p][3]);
                }
        }
        __syncthreads();
    }

    // Epilogue: v = cc - 2*dot = fma(acc, -2^-7, cc); store fp16 gmin
    int gq = l >> 2;
    #pragma unroll
    for (int mi = 0; mi < 2; mi++) {
        int rl0 = wm * 32 + mi * 16 + gq;
        float rmin0 = 3.4e38f, rmin8 = 3.4e38f;
        #pragma unroll
        for (int ni = 0; ni < 8; ni++) {
            int col = k0 + wn * 64 + ni * 8 + (l & 3) * 2;
            float cc0 = g_cc[col], cc1 = g_cc[col + 1];
            float m0 = fminf(fmaf(acc[mi][ni][0], -0.0078125f, cc0),
                             fmaf(acc[mi][ni][1], -0.0078125f, cc1));
            float m8 = fminf(fmaf(acc[mi][ni][2], -0.0078125f, cc0),
                             fmaf(acc[mi][ni][3], -0.0078125f, cc1));
            m0 = fminf(m0, __shfl_xor_sync(~0u, m0, 1));
            m0 = fminf(m0, __shfl_xor_sync(~0u, m0, 2));
            m8 = fminf(m8, __shfl_xor_sync(~0u, m8, 1));
            m8 = fminf(m8, __shfl_xor_sync(~0u, m8, 2));
            if ((l & 3) == 0) {
                size_t g = (size_t)((k0 + wn * 64 + ni * 8) >> 3);
                g_gmin[g * NQ + q0 + rl0] = __float2half(m0);
                g_gmin[g * NQ + q0 + rl0 + 8] = __float2half(m8);
                rmin0 = fminf(rmin0, m0);
                rmin8 = fminf(rmin8, m8);
            }
        }
        if ((l & 3) == 0) {
            atomicMin(&srowmin[rl0], fenc(rmin0));
            atomicMin(&srowmin[rl0 + 8], fenc(rmin8));
        }
    }
    __syncthreads();
    if (tid < PM) atomicMin(&g_m1[q0 + tid], srowmin[tid]);
}

// ---------------------------------------------------------------------------
// Phase 2a: flag groups with v <= m1 + EPS (fp16 gmin, fp32 threshold).
__global__ void __launch_bounds__(256) cand_kernel() {
    int q0 = blockIdx.x * 32;
    int wid = threadIdx.x >> 5, l = threadIdx.x & 31;
    int q = q0 + l;
    float thr = fdec(g_m1[q]) + EPS;
    for (int g = wid; g < NGRP; g += 8) {
        if (__half2float(g_gmin[(size_t)g * NQ + q]) <= thr) {
            int pos = atomicAdd(&g_ncand, 1);
            if (pos < CAND_CAP) g_cand[pos] = ((unsigned)q << 10) | (unsigned)g;
        }
    }
}

// Phase 2b: exact fp32 rescore of flagged groups (reference rounding formula,
// R1-validated); packed atomicMin => argmin with first-index tie-break.
__global__ void __launch_bounds__(256) rescore_kernel(const float* __restrict__ cb) {
    int gw = (blockIdx.x * blockDim.x + threadIdx.x) >> 5;
    int l = threadIdx.x & 31;
    int nwarps = (gridDim.x * blockDim.x) >> 5;
    int n = g_ncand; if (n > CAND_CAP) n = CAND_CAP;
    for (int c = gw; c < n; c += nwarps) {
        unsigned e = g_cand[c];
        int q = e >> 10, g = e & 1023;
        const float* zr = g_zt + (size_t)q * Dd;
        float zzv = g_zz[q];
        unsigned long long best = ~0ull;
        #pragma unroll 1
        for (int kk = 0; kk < 8; kk++) {
            int k = g * 8 + kk;
            const float* cr = cb + (size_t)k * Dd;
            float p = 0.0f;
            #pragma unroll
            for (int j = 0; j < 8; j++) {
                int d = l * 8 + j;
                p = __fadd_rn(p, __fmul_rn(zr[d], cr[d]));
            }
            #pragma unroll
            for (int o = 16; o > 0; o >>= 1)
                p = __fadd_rn(p, __shfl_xor_sync(~0u, p, o));
            float dd = __fadd_rn(__fadd_rn(zzv, __fmul_rn(-2.0f, p)), g_cc[k]);
            unsigned long long key =
                ((unsigned long long)__float_as_uint(dd) << 32) | (unsigned)k;
            if (key < best) best = key;
        }
        if (l == 0) atomicMin(&g_key[q], best);
    }
}

// ---------------------------------------------------------------------------
// Gather (+ index output fused): coalesced via smem transpose.
__global__ void gather_kernel(const float* __restrict__ z,
                              const float* __restrict__ cb,
                              float* __restrict__ out, long long out_size) {
    __shared__ float tile[32][33];
    __shared__ double ssum[256];
    int b = blockIdx.z, d0 = blockIdx.y * 32, t0 = blockIdx.x * 32;
    int tx = threadIdx.x, ty = threadIdx.y;
    int tid = ty * 32 + tx;
    #pragma unroll
    for (int r = 0; r < 4; r++) {
        int t = ty + r * 8;
        int q = b * Tt + t0 + t;
        int idx = (int)(unsigned)(g_key[q] & 0xffffffffu);
        tile[t][tx] = cb[(size_t)idx * Dd + d0 + tx];     // lane spans d: coalesced
    }
    // fused index write (one block column per (b,t0))
    if (blockIdx.y == 0 && tid < 32) {
        int q = b * Tt + t0 + tid;
        if (out_size >= NEL + NQ)
            out[NEL + q] = (float)(unsigned)(g_key[q] & 0xffffffffu);
    }
    __syncthreads();
    double local = 0.0;
    #pragma unroll
    for (int r = 0; r < 4; r++) {
        int d = d0 + ty + r * 8;
        long long o = ((long long)b * Dd + d) * Tt + t0 + tx;
        float zv = z[o];
        float zq = tile[tx][ty + r * 8];
        float diff = __fadd_rn(zq, -zv);
        if (o < out_size) out[o] = __fadd_rn(zv, diff);   // lane spans t: coalesced
        local += (double)__fmul_rn(diff, diff);
    }
    ssum[tid] = local;
    __syncthreads();
    for (int s = 128; s > 0; s >>= 1) {
        if (tid < s) ssum[tid] += ssum[tid + s];
        __syncthreads();
    }
    if (tid == 0) atomicAdd(&g_loss_sum, ssum[0]);
}

__global__ void finalize_kernel(float* __restrict__ out, long long out_size) {
    if (threadIdx.x == 0 && out_size >= NEL + NQ + 1) {
        float m = (float)(g_loss_sum / (double)NEL);
        out[NEL + NQ] = __fadd_rn(m, __fmul_rn(0.1f, m));
    }
}

// ---------------------------------------------------------------------------
extern "C" void kernel_launch(void* const* d_in, const int* in_sizes, int n_in,
                              void* d_out, int out_size) {
    const float* z  = (const float*)d_in[0];
    const float* cb = (const float*)d_in[1];
    if (n_in >= 2 && in_sizes[0] == Kk * Dd && in_sizes[1] == NEL) {
        const float* tmp = z; z = cb; cb = tmp;
    }
    float* out = (float*)d_out;
    long long osz = out_size;

    cudaFuncSetAttribute(phase1_kernel,
                         cudaFuncAttributeMaxDynamicSharedMemorySize, SMEM_DYN);

    prep_all_kernel<<<PREP_BLKS, 256>>>(z, cb);                         // 0
    dim3 g1(Kk / PN, NQ / PM);
    phase1_kernel<<<g1, 256, SMEM_DYN>>>();                             // 1
    cand_kernel<<<NQ / 32, 256>>>();                                    // 2
    rescore_kernel<<<512, 256>>>(cb);                                   // 3 (profiled)
    dim3 gg(Tt / 32, Dd / 32, Bq), tb(32, 8);
    gather_kernel<<<gg, tb>>>(z, cb, out, osz);                         // 4
    finalize_kernel<<<1, 32>>>(out, osz);                               // 5
}

// round 14
// speedup vs baseline: 1.7078x; 1.0904x over previous
#include <cuda_runtime.h>
#include <cuda_fp16.h>
#include <cstdint>

// Problem constants
#define Bq 8
#define Dd 256
#define Tt 2048
#define Kk 8192
#define NQ (Bq * Tt)          // 16384 queries
#define NEL (Bq * Dd * Tt)    // 4194304 z elements
#define NGRP (Kk / 8)         // 1024 groups of 8 codes

#define EPS 0.006f
#define CAND_CAP (2 * 1024 * 1024)

// Phase-1 tiling (R8 config: f16 inputs, f32 acc, PK=64, stagger)
#define PM 128
#define PN 128
#define PK 64
#define NCHUNK (Dd / PK)      // 4
#define ROWB 72               // smem row stride = 72 halves (64 data + 8 pad)
#define STAGE_BYTES ((PM + PN) * ROWB * 2)    // 36864
#define SMEM_DYN (2 * STAGE_BYTES)            // 73728

// prep_all block ranges
#define ZT_BLKS 4096          // z transpose tiles
#define CB_BLKS 2048          // codebook fp16 convert
#define CC_BLKS 256           // cc: 32 rows per block, smem-staged
#define IN_BLKS 64            // key/m1 init
#define ZZ_BLKS 64            // zz rows
#define PREP_BLKS (ZT_BLKS + CB_BLKS + CC_BLKS + IN_BLKS + ZZ_BLKS)

// Device scratch (static; runtime allocation is forbidden)
__device__ __align__(128) float  g_zt[NQ * Dd];     // z transposed [q][d] fp32
__device__ __align__(128) __half g_zhf[NQ * Dd];    // fp16 copy
__device__ __align__(128) __half g_cbhf[Kk * Dd];   // codebook * 256, fp16
__device__ __align__(128) __half g_gmin[(size_t)NGRP * NQ]; // fp16 approx (cc-2dot)
__device__ __align__(128) unsigned g_m1[NQ];        // per-query encoded fp32 min
__device__ __align__(128) float  g_zz[NQ];
__device__ __align__(128) float  g_cc[Kk];
__device__ __align__(128) unsigned long long g_key[NQ];
__device__ __align__(128) unsigned int g_cand[CAND_CAP];
__device__ int    g_ncand;
__device__ double g_loss_sum;

// ---------------------------------------------------------------------------
__device__ __forceinline__ uint32_t smem_u32(const void* p) {
    uint32_t a;
    asm("{ .reg .u64 t; cvta.to.shared.u64 t, %1; cvt.u32.u64 %0, t; }" : "=r"(a) : "l"(p));
    return a;
}
__device__ __forceinline__ unsigned fenc(float f) {
    int b = __float_as_int(f);
    return b >= 0 ? ((unsigned)b | 0x80000000u) : ~(unsigned)b;
}
__device__ __forceinline__ float fdec(unsigned k) {
    return (k & 0x80000000u) ? __int_as_float((int)(k & 0x7fffffffu))
                             : __int_as_float((int)~k);
}
#define CP16(dst, src) \
    asm volatile("cp.async.cg.shared.global [%0], [%1], 16;" :: "r"(dst), "l"(src) : "memory")
#define LDM4(r0, r1, r2, r3, a) \
    asm volatile("ldmatrix.sync.aligned.m8n8.x4.shared.b16 {%0,%1,%2,%3}, [%4];" \
        : "=r"(r0), "=r"(r1), "=r"(r2), "=r"(r3) : "r"(a))
#define MMA16816(c0, c1, c2, c3, a0, a1, a2, a3, b0, b1) \
    asm volatile("mma.sync.aligned.m16n8k16.row.col.f32.f16.f16.f32 " \
        "{%0,%1,%2,%3}, {%4,%5,%6,%7}, {%8,%9}, {%0,%1,%2,%3};" \
        : "+f"(c0), "+f"(c1), "+f"(c2), "+f"(c3) \
        : "r"(a0), "r"(a1), "r"(a2), "r"(a3), "r"(b0), "r"(b1))

// ---------------------------------------------------------------------------
// Mega-fused prep: z transpose + fp16 copies, cb fp16 convert, cc (smem-
// staged, sequential rounding preserved), zz, init. Disjoint block ranges.
__global__ void __launch_bounds__(256) prep_all_kernel(
    const float* __restrict__ z, const float* __restrict__ cb) {
    __shared__ float sbuf[32 * 257];   // CC staging (padded); ZT uses prefix
    int blk = blockIdx.x, tid = threadIdx.x;

    if (blk < ZT_BLKS) {
        // z transpose (B,D,T) -> [q][d], fp32 + fp16 (validated R5 layout)
        int b = blk >> 9, rem = blk & 511;
        int t0 = (rem & 63) * 32, d0 = (rem >> 6) * 32;
        int tx = tid & 31, ty = tid >> 5;          // 32 x 8
        #pragma unroll
        for (int r = 0; r < 4; r++) {
            int d = d0 + ty + r * 8;
            sbuf[(ty + r * 8) * 33 + tx] =
                z[(size_t)b * Dd * Tt + (size_t)d * Tt + t0 + tx];
        }
        __syncthreads();
        #pragma unroll
        for (int r = 0; r < 4; r++) {
            int tt = t0 + ty + r * 8;
            float v = sbuf[tx * 33 + ty + r * 8];
            size_t o = (size_t)(b * Tt + tt) * Dd + d0 + tx;
            g_zt[o] = v;
            g_zhf[o] = __float2half(v);
        }
        return;
    }
    blk -= ZT_BLKS;
    if (blk < CB_BLKS) {
        // codebook * 256 -> fp16 (exact pow2 rescale)
        #pragma unroll
        for (int k = 0; k < 4; k++) {
            int i = blk * 1024 + k * 256 + tid;
            g_cbhf[i] = __float2half(cb[i] * 256.0f);
        }
        return;
    }
    blk -= CB_BLKS;
    if (blk < CC_BLKS) {
        // cc: stage 32 rows coalesced into smem, then 32 sequential row sums
        // (reference fp32 rounding order preserved; bank-conflict-free pad)
        int r0 = blk * 32;                        // first codebook row
        const float* src = cb + (size_t)r0 * Dd;
        for (int i = tid; i < 32 * Dd; i += 256) {
            int row = i >> 8, d = i & 255;
            sbuf[row * 257 + d] = src[i];         // coalesced global read
        }
        __syncthreads();
        if (tid < 32) {
            const float* p = &sbuf[tid * 257];
            float acc = 0.0f;
            for (int d = 0; d < Dd; d++) {
                float v = p[d];
                acc = __fadd_rn(acc, __fmul_rn(v, v));
            }
            g_cc[r0 + tid] = acc;
        }
        return;
    }
    blk -= CC_BLKS;
    if (blk < IN_BLKS) {
        int i = blk * 256 + tid;
        g_key[i] = ~0ull;
        g_m1[i] = 0xFFFFFFFFu;
        if (blk == 0 && tid == 0) { g_loss_sum = 0.0; g_ncand = 0; }
        return;
    }
    blk -= IN_BLKS;
    {
        // zz: exact sequential fp32 sum of squares per query (coalesced in t)
        int i = blk * 256 + tid;
        int b = i / Tt, t = i % Tt;
        const float* p = z + (size_t)b * Dd * Tt + t;
        float acc = 0.0f;
        for (int d = 0; d < Dd; d++) {
            float v = p[(size_t)d * Tt];
            acc = __fadd_rn(acc, __fmul_rn(v, v));
        }
        g_zz[i] = acc;
    }
}

// ---------------------------------------------------------------------------
// Phase 1: fp16 mma.sync GEMM, f32 acc (R8 config, at the 512 MAC/cyc/SM
// legacy-HMMA instruction-rate wall). Epilogue: fp16 g_gmin + fp32 g_m1.
__global__ void __launch_bounds__(256, 2) phase1_kernel() {
    extern __shared__ __half smh[];
    __shared__ unsigned srowmin[PM];

    int tid = threadIdx.x, wid = tid >> 5, l = tid & 31;
    int wm = wid & 3, wn = wid >> 2;
    int q0 = blockIdx.y * PM, k0 = blockIdx.x * PN;

    if (tid < PM) srowmin[tid] = 0xFFFFFFFFu;

    float acc[2][8][4];
    #pragma unroll
    for (int mi = 0; mi < 2; mi++)
        #pragma unroll
        for (int ni = 0; ni < 8; ni++)
            #pragma unroll
            for (int j = 0; j < 4; j++) acc[mi][ni][j] = 0.0f;

    uint32_t s0 = smem_u32(&smh[0]);
    const uint32_t bOffB = (uint32_t)PM * ROWB * 2;

    int rA = wm * 32 + (l & 15), hA = (l >> 4) & 1;
    int rB = wn * 64 + (l & 15), hB = (l >> 4) & 1;
    uint32_t aoff = (uint32_t)(rA * ROWB + hA * 8) * 2;
    uint32_t boff = (uint32_t)(rB * ROWB + hB * 8) * 2;
    int rot = wid & 3;                       // per-warp k16-phase rotation

    auto issue = [&](int c) {
        uint32_t st = s0 + (uint32_t)(c & 1) * STAGE_BYTES;
        int d0 = c * PK;
        #pragma unroll
        for (int i = 0; i < 8; i++) {
            int idx = tid + i * 256;          // 0..2047
            int row = idx >> 3, sec = idx & 7;
            const __half* src = (row < PM)
                ? g_zhf + (size_t)(q0 + row) * Dd + d0 + sec * 8
                : g_cbhf + (size_t)(k0 + row - PM) * Dd + d0 + sec * 8;
            uint32_t dst = st + ((row < PM)
                ? (uint32_t)(row * ROWB + sec * 8) * 2
                : (bOffB + (uint32_t)((row - PM) * ROWB + sec * 8) * 2));
            CP16(dst, src);
        }
        asm volatile("cp.async.commit_group;" ::: "memory");
    };

    issue(0);
    for (int c = 0; c < NCHUNK; c++) {
        if (c + 1 < NCHUNK) {
            issue(c + 1);
            asm volatile("cp.async.wait_group 1;" ::: "memory");
        } else {
            asm volatile("cp.async.wait_group 0;" ::: "memory");
        }
        __syncthreads();
        uint32_t st = s0 + (uint32_t)(c & 1) * STAGE_BYTES;
        uint32_t bA = st, bB = st + bOffB;
        #pragma unroll
        for (int ks = 0; ks < 4; ks++) {
            int kk = (ks + rot) & 3;
            uint32_t kb = (uint32_t)(kk * 16) * 2;
            uint32_t af[2][4], bf[4][4];
            #pragma unroll
            for (int mi = 0; mi < 2; mi++)
                LDM4(af[mi][0], af[mi][1], af[mi][2], af[mi][3],
                     bA + aoff + (uint32_t)(mi * 16 * ROWB) * 2 + kb);
            #pragma unroll
            for (int p = 0; p < 4; p++)
                LDM4(bf[p][0], bf[p][1], bf[p][2], bf[p][3],
                     bB + boff + (uint32_t)(p * 16 * ROWB) * 2 + kb);
            #pragma unroll
            for (int mi = 0; mi < 2; mi++)
                #pragma unroll
                for (int p = 0; p < 4; p++) {
                    MMA16816(acc[mi][2*p][0], acc[mi][2*p][1], acc[mi][2*p][2], acc[mi][2*p][3],
                             af[mi][0], af[mi][1], af[mi][2], af[mi][3],
                             bf[p][0], bf[p][2]);
                    MMA16816(acc[mi][2*p+1][0], acc[mi][2*p+1][1], acc[mi][2*p+1][2], acc[mi][2*p+1][3],
                             af[mi][0], af[mi][1], af[mi][2], af[mi][3],
                             bf[p][1], bf[p][3]);
                }
        }
        __syncthreads();
    }

    // Epilogue: v = cc - 2*dot = fma(acc, -2^-7, cc); store fp16 gmin
    int gq = l >> 2;
    #pragma unroll
    for (int mi = 0; mi < 2; mi++) {
        int rl0 = wm * 32 + mi * 16 + gq;
        float rmin0 = 3.4e38f, rmin8 = 3.4e38f;
        #pragma unroll
        for (int ni = 0; ni < 8; ni++) {
            int col = k0 + wn * 64 + ni * 8 + (l & 3) * 2;
            float cc0 = g_cc[col], cc1 = g_cc[col + 1];
            float m0 = fminf(fmaf(acc[mi][ni][0], -0.0078125f, cc0),
                             fmaf(acc[mi][ni][1], -0.0078125f, cc1));
            float m8 = fminf(fmaf(acc[mi][ni][2], -0.0078125f, cc0),
                             fmaf(acc[mi][ni][3], -0.0078125f, cc1));
            m0 = fminf(m0, __shfl_xor_sync(~0u, m0, 1));
            m0 = fminf(m0, __shfl_xor_sync(~0u, m0, 2));
            m8 = fminf(m8, __shfl_xor_sync(~0u, m8, 1));
            m8 = fminf(m8, __shfl_xor_sync(~0u, m8, 2));
            if ((l & 3) == 0) {
                size_t g = (size_t)((k0 + wn * 64 + ni * 8) >> 3);
                g_gmin[g * NQ + q0 + rl0] = __float2half(m0);
                g_gmin[g * NQ + q0 + rl0 + 8] = __float2half(m8);
                rmin0 = fminf(rmin0, m0);
                rmin8 = fminf(rmin8, m8);
            }
        }
        if ((l & 3) == 0) {
            atomicMin(&srowmin[rl0], fenc(rmin0));
            atomicMin(&srowmin[rl0 + 8], fenc(rmin8));
        }
    }
    __syncthreads();
    if (tid < PM) atomicMin(&g_m1[q0 + tid], srowmin[tid]);
}

// ---------------------------------------------------------------------------
// Phase 2a: flag groups with v <= m1 + EPS (fp16 gmin, fp32 threshold).
__global__ void __launch_bounds__(256) cand_kernel() {
    int q0 = blockIdx.x * 32;
    int wid = threadIdx.x >> 5, l = threadIdx.x & 31;
    int q = q0 + l;
    float thr = fdec(g_m1[q]) + EPS;
    for (int g = wid; g < NGRP; g += 8) {
        if (__half2float(g_gmin[(size_t)g * NQ + q]) <= thr) {
            int pos = atomicAdd(&g_ncand, 1);
            if (pos < CAND_CAP) g_cand[pos] = ((unsigned)q << 10) | (unsigned)g;
        }
    }
}

// Phase 2b: exact fp32 rescore, lane-parallel: lane l -> code l/4, dim
// quarter l%4 (16 float4 loads, 4 ILP chains). 2 SHFL to form dots, 3-step
// u64-min tree => group best key; atomicMin preserves first-index tie-break.
__global__ void __launch_bounds__(256) rescore_kernel(const float* __restrict__ cb) {
    int gw = (blockIdx.x * blockDim.x + threadIdx.x) >> 5;
    int l = threadIdx.x & 31;
    int nwarps = (gridDim.x * blockDim.x) >> 5;
    int n = g_ncand; if (n > CAND_CAP) n = CAND_CAP;
    for (int c = gw; c < n; c += nwarps) {
        unsigned e = g_cand[c];
        int q = e >> 10, g = e & 1023;
        int k = g * 8 + (l >> 2);
        const float4* zr = reinterpret_cast<const float4*>(g_zt + (size_t)q * Dd)
                           + (l & 3) * 16;
        const float4* cr = reinterpret_cast<const float4*>(cb + (size_t)k * Dd)
                           + (l & 3) * 16;
        float p0 = 0.0f, p1 = 0.0f, p2 = 0.0f, p3 = 0.0f;
        #pragma unroll
        for (int j = 0; j < 16; j++) {
            float4 a = zr[j], b = cr[j];
            p0 = __fadd_rn(p0, __fmul_rn(a.x, b.x));
            p1 = __fadd_rn(p1, __fmul_rn(a.y, b.y));
            p2 = __fadd_rn(p2, __fmul_rn(a.z, b.z));
            p3 = __fadd_rn(p3, __fmul_rn(a.w, b.w));
        }
        float p = __fadd_rn(__fadd_rn(p0, p1), __fadd_rn(p2, p3));
        p = __fadd_rn(p, __shfl_xor_sync(~0u, p, 1));
        p = __fadd_rn(p, __shfl_xor_sync(~0u, p, 2));
        unsigned long long key = ~0ull;
        if ((l & 3) == 0) {
            float dd = __fadd_rn(__fadd_rn(g_zz[q], __fmul_rn(-2.0f, p)), g_cc[k]);
            key = ((unsigned long long)__float_as_uint(dd) << 32) | (unsigned)k;
        }
        #pragma unroll
        for (int o = 4; o < 32; o <<= 1) {
            unsigned long long other = __shfl_xor_sync(~0u, key, o);
            if (other < key) key = other;
        }
        if (l == 0) atomicMin(&g_key[q], key);
    }
}

// ---------------------------------------------------------------------------
// Gather (+ index output fused): coalesced via smem transpose.
__global__ void gather_kernel(const float* __restrict__ z,
                              const float* __restrict__ cb,
                              float* __restrict__ out, long long out_size) {
    __shared__ float tile[32][33];
    __shared__ double ssum[256];
    int b = blockIdx.z, d0 = blockIdx.y * 32, t0 = blockIdx.x * 32;
    int tx = threadIdx.x, ty = threadIdx.y;
    int tid = ty * 32 + tx;
    #pragma unroll
    for (int r = 0; r < 4; r++) {
        int t = ty + r * 8;
        int q = b * Tt + t0 + t;
        int idx = (int)(unsigned)(g_key[q] & 0xffffffffu);
        tile[t][tx] = cb[(size_t)idx * Dd + d0 + tx];     // lane spans d: coalesced
    }
    if (blockIdx.y == 0 && tid < 32) {
        int q = b * Tt + t0 + tid;
        if (out_size >= NEL + NQ)
            out[NEL + q] = (float)(unsigned)(g_key[q] & 0xffffffffu);
    }
    __syncthreads();
    double local = 0.0;
    #pragma unroll
    for (int r = 0; r < 4; r++) {
        int d = d0 + ty + r * 8;
        long long o = ((long long)b * Dd + d) * Tt + t0 + tx;
        float zv = z[o];
        float zq = tile[tx][ty + r * 8];
        float diff = __fadd_rn(zq, -zv);
        if (o < out_size) out[o] = __fadd_rn(zv, diff);   // lane spans t: coalesced
        local += (double)__fmul_rn(diff, diff);
    }
    ssum[tid] = local;
    __syncthreads();
    for (int s = 128; s > 0; s >>= 1) {
        if (tid < s) ssum[tid] += ssum[tid + s];
        __syncthreads();
    }
    if (tid == 0) atomicAdd(&g_loss_sum, ssum[0]);
}

__global__ void finalize_kernel(float* __restrict__ out, long long out_size) {
    if (threadIdx.x == 0 && out_size >= NEL + NQ + 1) {
        float m = (float)(g_loss_sum / (double)NEL);
        out[NEL + NQ] = __fadd_rn(m, __fmul_rn(0.1f, m));
    }
}

// ---------------------------------------------------------------------------
extern "C" void kernel_launch(void* const* d_in, const int* in_sizes, int n_in,
                              void* d_out, int out_size) {
    const float* z  = (const float*)d_in[0];
    const float* cb = (const float*)d_in[1];
    if (n_in >= 2 && in_sizes[0] == Kk * Dd && in_sizes[1] == NEL) {
        const float* tmp = z; z = cb; cb = tmp;
    }
    float* out = (float*)d_out;
    long long osz = out_size;

    cudaFuncSetAttribute(phase1_kernel,
                         cudaFuncAttributeMaxDynamicSharedMemorySize, SMEM_DYN);

    prep_all_kernel<<<PREP_BLKS, 256>>>(z, cb);                         // 0
    dim3 g1(Kk / PN, NQ / PM);
    phase1_kernel<<<g1, 256, SMEM_DYN>>>();                             // 1
    cand_kernel<<<NQ / 32, 256>>>();                                    // 2
    rescore_kernel<<<1024, 256>>>(cb);                                  // 3 (profiled)
    dim3 gg(Tt / 32, Dd / 32, Bq), tb(32, 8);
    gather_kernel<<<gg, tb>>>(z, cb, out, osz);                         // 4
    finalize_kernel<<<1, 32>>>(out, osz);                               // 5
}

// round 15
// speedup vs baseline: 1.9150x; 1.1214x over previous
#include <cuda_runtime.h>
#include <cuda_fp16.h>
#include <cstdint>

// Problem constants
#define Bq 8
#define Dd 256
#define Tt 2048
#define Kk 8192
#define NQ (Bq * Tt)          // 16384 queries
#define NEL (Bq * Dd * Tt)    // 4194304 z elements
#define NGRP (Kk / 8)         // 1024 groups of 8 codes

#define EPS 0.006f
#define CAND_CAP (2 * 1024 * 1024)

// Phase-1 tiling (R8 config: f16 inputs, f32 acc, PK=64, stagger)
#define PM 128
#define PN 128
#define PK 64
#define NCHUNK (Dd / PK)      // 4
#define ROWB 72               // smem row stride = 72 halves (64 data + 8 pad)
#define STAGE_BYTES ((PM + PN) * ROWB * 2)    // 36864
#define SMEM_DYN (2 * STAGE_BYTES)            // 73728

// prep_all block ranges
#define ZT_BLKS 4096          // z transpose tiles
#define CB_BLKS 2048          // codebook fp16 convert
#define CC_BLKS 256           // cc: 32 rows per block, smem-staged
#define IN_BLKS 64            // key/m1 init
#define ZZ_BLKS 64            // zz rows
#define PREP_BLKS (ZT_BLKS + CB_BLKS + CC_BLKS + IN_BLKS + ZZ_BLKS)

// Device scratch (static; runtime allocation is forbidden)
__device__ __align__(128) float  g_zt[NQ * Dd];     // z transposed [q][d] fp32
__device__ __align__(128) __half g_zhf[NQ * Dd];    // fp16 copy
__device__ __align__(128) __half g_cbhf[Kk * Dd];   // codebook * 256, fp16
__device__ __align__(128) __half g_gmin[(size_t)NGRP * NQ]; // fp16 approx (cc-2dot)
__device__ __align__(128) unsigned g_m1[NQ];        // per-query encoded fp32 min
__device__ __align__(128) float  g_zz[NQ];
__device__ __align__(128) float  g_cc[Kk];
__device__ __align__(128) unsigned long long g_key[NQ];
__device__ __align__(128) unsigned int g_cand[CAND_CAP];
__device__ int    g_ncand;
__device__ double g_loss_sum;

// ---------------------------------------------------------------------------
__device__ __forceinline__ uint32_t smem_u32(const void* p) {
    uint32_t a;
    asm("{ .reg .u64 t; cvta.to.shared.u64 t, %1; cvt.u32.u64 %0, t; }" : "=r"(a) : "l"(p));
    return a;
}
__device__ __forceinline__ unsigned fenc(float f) {
    int b = __float_as_int(f);
    return b >= 0 ? ((unsigned)b | 0x80000000u) : ~(unsigned)b;
}
__device__ __forceinline__ float fdec(unsigned k) {
    return (k & 0x80000000u) ? __int_as_float((int)(k & 0x7fffffffu))
                             : __int_as_float((int)~k);
}
#define CP16(dst, src) \
    asm volatile("cp.async.cg.shared.global [%0], [%1], 16;" :: "r"(dst), "l"(src) : "memory")
#define LDM4(r0, r1, r2, r3, a) \
    asm volatile("ldmatrix.sync.aligned.m8n8.x4.shared.b16 {%0,%1,%2,%3}, [%4];" \
        : "=r"(r0), "=r"(r1), "=r"(r2), "=r"(r3) : "r"(a))
#define MMA16816(c0, c1, c2, c3, a0, a1, a2, a3, b0, b1) \
    asm volatile("mma.sync.aligned.m16n8k16.row.col.f32.f16.f16.f32 " \
        "{%0,%1,%2,%3}, {%4,%5,%6,%7}, {%8,%9}, {%0,%1,%2,%3};" \
        : "+f"(c0), "+f"(c1), "+f"(c2), "+f"(c3) \
        : "r"(a0), "r"(a1), "r"(a2), "r"(a3), "r"(b0), "r"(b1))

// ---------------------------------------------------------------------------
// Mega-fused prep: z transpose + fp16 copies, cb fp16 convert, cc (smem-
// staged, sequential rounding preserved), zz, init. Disjoint block ranges.
__global__ void __launch_bounds__(256) prep_all_kernel(
    const float* __restrict__ z, const float* __restrict__ cb) {
    __shared__ float sbuf[32 * 257];   // CC staging (padded); ZT uses prefix
    int blk = blockIdx.x, tid = threadIdx.x;

    if (blk < ZT_BLKS) {
        // z transpose (B,D,T) -> [q][d], fp32 + fp16 (validated R5 layout)
        int b = blk >> 9, rem = blk & 511;
        int t0 = (rem & 63) * 32, d0 = (rem >> 6) * 32;
        int tx = tid & 31, ty = tid >> 5;          // 32 x 8
        #pragma unroll
        for (int r = 0; r < 4; r++) {
            int d = d0 + ty + r * 8;
            sbuf[(ty + r * 8) * 33 + tx] =
                z[(size_t)b * Dd * Tt + (size_t)d * Tt + t0 + tx];
        }
        __syncthreads();
        #pragma unroll
        for (int r = 0; r < 4; r++) {
            int tt = t0 + ty + r * 8;
            float v = sbuf[tx * 33 + ty + r * 8];
            size_t o = (size_t)(b * Tt + tt) * Dd + d0 + tx;
            g_zt[o] = v;
            g_zhf[o] = __float2half(v);
        }
        return;
    }
    blk -= ZT_BLKS;
    if (blk < CB_BLKS) {
        // codebook * 256 -> fp16 (exact pow2 rescale)
        #pragma unroll
        for (int k = 0; k < 4; k++) {
            int i = blk * 1024 + k * 256 + tid;
            g_cbhf[i] = __float2half(cb[i] * 256.0f);
        }
        return;
    }
    blk -= CB_BLKS;
    if (blk < CC_BLKS) {
        // cc: stage 32 rows coalesced into smem, then 32 sequential row sums
        int r0 = blk * 32;
        const float* src = cb + (size_t)r0 * Dd;
        for (int i = tid; i < 32 * Dd; i += 256) {
            int row = i >> 8, d = i & 255;
            sbuf[row * 257 + d] = src[i];
        }
        __syncthreads();
        if (tid < 32) {
            const float* p = &sbuf[tid * 257];
            float acc = 0.0f;
            for (int d = 0; d < Dd; d++) {
                float v = p[d];
                acc = __fadd_rn(acc, __fmul_rn(v, v));
            }
            g_cc[r0 + tid] = acc;
        }
        return;
    }
    blk -= CC_BLKS;
    if (blk < IN_BLKS) {
        int i = blk * 256 + tid;
        g_key[i] = ~0ull;
        g_m1[i] = 0xFFFFFFFFu;
        if (blk == 0 && tid == 0) { g_loss_sum = 0.0; g_ncand = 0; }
        return;
    }
    blk -= IN_BLKS;
    {
        // zz: exact sequential fp32 sum of squares per query (coalesced in t)
        int i = blk * 256 + tid;
        int b = i / Tt, t = i % Tt;
        const float* p = z + (size_t)b * Dd * Tt + t;
        float acc = 0.0f;
        for (int d = 0; d < Dd; d++) {
            float v = p[(size_t)d * Tt];
            acc = __fadd_rn(acc, __fmul_rn(v, v));
        }
        g_zz[i] = acc;
    }
}

// ---------------------------------------------------------------------------
// Phase 1: fp16 mma.sync GEMM, f32 acc (R8 config, at the 512 MAC/cyc/SM
// legacy-HMMA instruction-rate wall). Epilogue: fp16 g_gmin + fp32 g_m1.
__global__ void __launch_bounds__(256, 2) phase1_kernel() {
    extern __shared__ __half smh[];
    __shared__ unsigned srowmin[PM];

    int tid = threadIdx.x, wid = tid >> 5, l = tid & 31;
    int wm = wid & 3, wn = wid >> 2;
    int q0 = blockIdx.y * PM, k0 = blockIdx.x * PN;

    if (tid < PM) srowmin[tid] = 0xFFFFFFFFu;

    float acc[2][8][4];
    #pragma unroll
    for (int mi = 0; mi < 2; mi++)
        #pragma unroll
        for (int ni = 0; ni < 8; ni++)
            #pragma unroll
            for (int j = 0; j < 4; j++) acc[mi][ni][j] = 0.0f;

    uint32_t s0 = smem_u32(&smh[0]);
    const uint32_t bOffB = (uint32_t)PM * ROWB * 2;

    int rA = wm * 32 + (l & 15), hA = (l >> 4) & 1;
    int rB = wn * 64 + (l & 15), hB = (l >> 4) & 1;
    uint32_t aoff = (uint32_t)(rA * ROWB + hA * 8) * 2;
    uint32_t boff = (uint32_t)(rB * ROWB + hB * 8) * 2;
    int rot = wid & 3;                       // per-warp k16-phase rotation

    auto issue = [&](int c) {
        uint32_t st = s0 + (uint32_t)(c & 1) * STAGE_BYTES;
        int d0 = c * PK;
        #pragma unroll
        for (int i = 0; i < 8; i++) {
            int idx = tid + i * 256;          // 0..2047
            int row = idx >> 3, sec = idx & 7;
            const __half* src = (row < PM)
                ? g_zhf + (size_t)(q0 + row) * Dd + d0 + sec * 8
                : g_cbhf + (size_t)(k0 + row - PM) * Dd + d0 + sec * 8;
            uint32_t dst = st + ((row < PM)
                ? (uint32_t)(row * ROWB + sec * 8) * 2
                : (bOffB + (uint32_t)((row - PM) * ROWB + sec * 8) * 2));
            CP16(dst, src);
        }
        asm volatile("cp.async.commit_group;" ::: "memory");
    };

    issue(0);
    for (int c = 0; c < NCHUNK; c++) {
        if (c + 1 < NCHUNK) {
            issue(c + 1);
            asm volatile("cp.async.wait_group 1;" ::: "memory");
        } else {
            asm volatile("cp.async.wait_group 0;" ::: "memory");
        }
        __syncthreads();
        uint32_t st = s0 + (uint32_t)(c & 1) * STAGE_BYTES;
        uint32_t bA = st, bB = st + bOffB;
        #pragma unroll
        for (int ks = 0; ks < 4; ks++) {
            int kk = (ks + rot) & 3;
            uint32_t kb = (uint32_t)(kk * 16) * 2;
            uint32_t af[2][4], bf[4][4];
            #pragma unroll
            for (int mi = 0; mi < 2; mi++)
                LDM4(af[mi][0], af[mi][1], af[mi][2], af[mi][3],
                     bA + aoff + (uint32_t)(mi * 16 * ROWB) * 2 + kb);
            #pragma unroll
            for (int p = 0; p < 4; p++)
                LDM4(bf[p][0], bf[p][1], bf[p][2], bf[p][3],
                     bB + boff + (uint32_t)(p * 16 * ROWB) * 2 + kb);
            #pragma unroll
            for (int mi = 0; mi < 2; mi++)
                #pragma unroll
                for (int p = 0; p < 4; p++) {
                    MMA16816(acc[mi][2*p][0], acc[mi][2*p][1], acc[mi][2*p][2], acc[mi][2*p][3],
                             af[mi][0], af[mi][1], af[mi][2], af[mi][3],
                             bf[p][0], bf[p][2]);
                    MMA16816(acc[mi][2*p+1][0], acc[mi][2*p+1][1], acc[mi][2*p+1][2], acc[mi][2*p+1][3],
                             af[mi][0], af[mi][1], af[mi][2], af[mi][3],
                             bf[p][1], bf[p][3]);
                }
        }
        __syncthreads();
    }

    // Epilogue: v = cc - 2*dot = fma(acc, -2^-7, cc); store fp16 gmin
    int gq = l >> 2;
    #pragma unroll
    for (int mi = 0; mi < 2; mi++) {
        int rl0 = wm * 32 + mi * 16 + gq;
        float rmin0 = 3.4e38f, rmin8 = 3.4e38f;
        #pragma unroll
        for (int ni = 0; ni < 8; ni++) {
            int col = k0 + wn * 64 + ni * 8 + (l & 3) * 2;
            float cc0 = g_cc[col], cc1 = g_cc[col + 1];
            float m0 = fminf(fmaf(acc[mi][ni][0], -0.0078125f, cc0),
                             fmaf(acc[mi][ni][1], -0.0078125f, cc1));
            float m8 = fminf(fmaf(acc[mi][ni][2], -0.0078125f, cc0),
                             fmaf(acc[mi][ni][3], -0.0078125f, cc1));
            m0 = fminf(m0, __shfl_xor_sync(~0u, m0, 1));
            m0 = fminf(m0, __shfl_xor_sync(~0u, m0, 2));
            m8 = fminf(m8, __shfl_xor_sync(~0u, m8, 1));
            m8 = fminf(m8, __shfl_xor_sync(~0u, m8, 2));
            if ((l & 3) == 0) {
                size_t g = (size_t)((k0 + wn * 64 + ni * 8) >> 3);
                g_gmin[g * NQ + q0 + rl0] = __float2half(m0);
                g_gmin[g * NQ + q0 + rl0 + 8] = __float2half(m8);
                rmin0 = fminf(rmin0, m0);
                rmin8 = fminf(rmin8, m8);
            }
        }
        if ((l & 3) == 0) {
            atomicMin(&srowmin[rl0], fenc(rmin0));
            atomicMin(&srowmin[rl0 + 8], fenc(rmin8));
        }
    }
    __syncthreads();
    if (tid < PM) atomicMin(&g_m1[q0 + tid], srowmin[tid]);
}

// ---------------------------------------------------------------------------
// Phase 2a: flag groups with v <= m1 + EPS (fp16 gmin, fp32 threshold).
__global__ void __launch_bounds__(256) cand_kernel() {
    int q0 = blockIdx.x * 32;
    int wid = threadIdx.x >> 5, l = threadIdx.x & 31;
    int q = q0 + l;
    float thr = fdec(g_m1[q]) + EPS;
    for (int g = wid; g < NGRP; g += 8) {
        if (__half2float(g_gmin[(size_t)g * NQ + q]) <= thr) {
            int pos = atomicAdd(&g_ncand, 1);
            if (pos < CAND_CAP) g_cand[pos] = ((unsigned)q << 10) | (unsigned)g;
        }
    }
}

// Phase 2b: exact fp32 rescore, lane-parallel over codes, INTERLEAVED dim
// mapping: lane l -> code l/4, 16B chunks j*4+(l&3). Each load instruction
// covers 8 rows x 64B contiguous segments (fully coalesced), 4 ILP chains
// per lane; 2 SHFL to form dots + 3-step u64-min tree; atomicMin preserves
// first-index tie-break (exact d formula unchanged from R1).
__global__ void __launch_bounds__(256) rescore_kernel(const float* __restrict__ cb) {
    int gw = (blockIdx.x * blockDim.x + threadIdx.x) >> 5;
    int l = threadIdx.x & 31;
    int nwarps = (gridDim.x * blockDim.x) >> 5;
    int n = g_ncand; if (n > CAND_CAP) n = CAND_CAP;
    int lq = l & 3;
    for (int c = gw; c < n; c += nwarps) {
        unsigned e = g_cand[c];
        int q = e >> 10, g = e & 1023;
        int k = g * 8 + (l >> 2);
        const float4* zr = reinterpret_cast<const float4*>(g_zt + (size_t)q * Dd);
        const float4* cr = reinterpret_cast<const float4*>(cb + (size_t)k * Dd);
        float p0 = 0.0f, p1 = 0.0f, p2 = 0.0f, p3 = 0.0f;
        #pragma unroll
        for (int j = 0; j < 16; j++) {
            float4 a = zr[j * 4 + lq], b = cr[j * 4 + lq];   // interleaved
            p0 = __fadd_rn(p0, __fmul_rn(a.x, b.x));
            p1 = __fadd_rn(p1, __fmul_rn(a.y, b.y));
            p2 = __fadd_rn(p2, __fmul_rn(a.z, b.z));
            p3 = __fadd_rn(p3, __fmul_rn(a.w, b.w));
        }
        float p = __fadd_rn(__fadd_rn(p0, p1), __fadd_rn(p2, p3));
        p = __fadd_rn(p, __shfl_xor_sync(~0u, p, 1));
        p = __fadd_rn(p, __shfl_xor_sync(~0u, p, 2));
        unsigned long long key = ~0ull;
        if (lq == 0) {
            float dd = __fadd_rn(__fadd_rn(g_zz[q], __fmul_rn(-2.0f, p)), g_cc[k]);
            key = ((unsigned long long)__float_as_uint(dd) << 32) | (unsigned)k;
        }
        #pragma unroll
        for (int o = 4; o < 32; o <<= 1) {
            unsigned long long other = __shfl_xor_sync(~0u, key, o);
            if (other < key) key = other;
        }
        if (l == 0) atomicMin(&g_key[q], key);
    }
}

// ---------------------------------------------------------------------------
// Gather (+ index output fused): coalesced via smem transpose.
__global__ void gather_kernel(const float* __restrict__ z,
                              const float* __restrict__ cb,
                              float* __restrict__ out, long long out_size) {
    __shared__ float tile[32][33];
    __shared__ double ssum[256];
    int b = blockIdx.z, d0 = blockIdx.y * 32, t0 = blockIdx.x * 32;
    int tx = threadIdx.x, ty = threadIdx.y;
    int tid = ty * 32 + tx;
    #pragma unroll
    for (int r = 0; r < 4; r++) {
        int t = ty + r * 8;
        int q = b * Tt + t0 + t;
        int idx = (int)(unsigned)(g_key[q] & 0xffffffffu);
        tile[t][tx] = cb[(size_t)idx * Dd + d0 + tx];     // lane spans d: coalesced
    }
    if (blockIdx.y == 0 && tid < 32) {
        int q = b * Tt + t0 + tid;
        if (out_size >= NEL + NQ)
            out[NEL + q] = (float)(unsigned)(g_key[q] & 0xffffffffu);
    }
    __syncthreads();
    double local = 0.0;
    #pragma unroll
    for (int r = 0; r < 4; r++) {
        int d = d0 + ty + r * 8;
        long long o = ((long long)b * Dd + d) * Tt + t0 + tx;
        float zv = z[o];
        float zq = tile[tx][ty + r * 8];
        float diff = __fadd_rn(zq, -zv);
        if (o < out_size) out[o] = __fadd_rn(zv, diff);   // lane spans t: coalesced
        local += (double)__fmul_rn(diff, diff);
    }
    ssum[tid] = local;
    __syncthreads();
    for (int s = 128; s > 0; s >>= 1) {
        if (tid < s) ssum[tid] += ssum[tid + s];
        __syncthreads();
    }
    if (tid == 0) atomicAdd(&g_loss_sum, ssum[0]);
}

__global__ void finalize_kernel(float* __restrict__ out, long long out_size) {
    if (threadIdx.x == 0 && out_size >= NEL + NQ + 1) {
        float m = (float)(g_loss_sum / (double)NEL);
        out[NEL + NQ] = __fadd_rn(m, __fmul_rn(0.1f, m));
    }
}

// ---------------------------------------------------------------------------
extern "C" void kernel_launch(void* const* d_in, const int* in_sizes, int n_in,
                              void* d_out, int out_size) {
    const float* z  = (const float*)d_in[0];
    const float* cb = (const float*)d_in[1];
    if (n_in >= 2 && in_sizes[0] == Kk * Dd && in_sizes[1] == NEL) {
        const float* tmp = z; z = cb; cb = tmp;
    }
    float* out = (float*)d_out;
    long long osz = out_size;

    cudaFuncSetAttribute(phase1_kernel,
                         cudaFuncAttributeMaxDynamicSharedMemorySize, SMEM_DYN);

    prep_all_kernel<<<PREP_BLKS, 256>>>(z, cb);                         // 0
    dim3 g1(Kk / PN, NQ / PM);
    phase1_kernel<<<g1, 256, SMEM_DYN>>>();                             // 1
    cand_kernel<<<NQ / 32, 256>>>();                                    // 2
    rescore_kernel<<<2048, 256>>>(cb);                                  // 3 (profiled)
    dim3 gg(Tt / 32, Dd / 32, Bq), tb(32, 8);
    gather_kernel<<<gg, tb>>>(z, cb, out, osz);                         // 4
    finalize_kernel<<<1, 32>>>(out, osz);                               // 5
}